// round 14
// baseline (speedup 1.0000x reference)
#include <cuda_runtime.h>
#include <cstdint>

// Depthwise conv1d, K=7, 'same' padding, softmax over taps.
// x: (B, C, T) fp32; weight: (H, 1, 7); head for channel c is c % H (H=16).
//
// Persistent grid-stride kernel, SOFTWARE-PIPELINED with double-buffered smem:
//   iter j: STS tile j -> buf[j&1]; ONE barrier; prefetch tile j+1 LDGs;
//           compute tile j (middle chunk from registers); swap buffers.
// Softmax for all 16 heads computed once per CTA in the prologue.
// GRID=2048 -> exactly 16 tiles per CTA (perfectly balanced).

#define KSIZE 7
#define TILE 2048
#define HALF (TILE / 2)
#define THREADS 256
#define SHIFT 4    // s[buf][SHIFT + i] = x[t0 + i]; halo lives at [1..3]
#define T_LEN 4096
#define NTILES 32768           // rows(16384) * 2 tiles per row
#define GRID 2048
#define NT (NTILES / GRID)     // 16 tiles per CTA
#define BUFSZ (SHIFT + TILE + 4)

__global__ __launch_bounds__(THREADS, 6)
void lconv1d_pipe_kernel(const float* __restrict__ x,
                         const float* __restrict__ wraw,
                         float* __restrict__ out) {
    __shared__ float s[2][BUFSZ];
    __shared__ __align__(16) float sw[16][8];   // all heads, padded to 8

    const int tid = threadIdx.x;
    const int p0 = tid * 4;
    const int p1 = p0 + HALF;

    // Prologue: softmax for all 16 heads, once per CTA (threads 0..15).
    if (tid < 16) {
        float v[KSIZE];
        float m = -1e30f;
        #pragma unroll
        for (int k = 0; k < KSIZE; k++) {
            v[k] = __ldg(&wraw[tid * KSIZE + k]);
            m = fmaxf(m, v[k]);
        }
        float sum = 0.f;
        #pragma unroll
        for (int k = 0; k < KSIZE; k++) sum += __expf(v[k] - m);
        const float inv = 1.f / sum;
        #pragma unroll
        for (int k = 0; k < KSIZE; k++) sw[tid][k] = __expf(v[k] - m) * inv;
        sw[tid][7] = 0.f;
    }
    // (sw visibility covered by the first in-loop __syncthreads.)

    // Prologue: load tile 0 into registers.
    int tile = blockIdx.x;
    {
    }
    size_t base = ((size_t)(tile >> 1)) * T_LEN + (tile & 1) * TILE;
    float4 v0 = *reinterpret_cast<const float4*>(x + base + p0);
    float4 v1 = *reinterpret_cast<const float4*>(x + base + p1);
    float hl = 0.f, hr = 0.f;
    if (tid < 3) {
        const int t0 = (tile & 1) * TILE;
        if (t0 > 0)            hl = x[base - 3 + tid];
        if (t0 + TILE < T_LEN) hr = x[base + TILE + tid];
    }

    int buf = 0;

    #pragma unroll 1
    for (int i = 0; i < NT; i++) {
        // Publish current tile into smem (aligned STS.128 + halo).
        *reinterpret_cast<float4*>(&s[buf][SHIFT + p0]) = v0;
        *reinterpret_cast<float4*>(&s[buf][SHIFT + p1]) = v1;
        if (tid < 3) {
            s[buf][1 + tid] = hl;
            s[buf][SHIFT + TILE + tid] = hr;
        }

        __syncthreads();   // the ONLY barrier per tile

        const int row = tile >> 1;

        // Prefetch next tile (LDGs in flight during this tile's compute).
        float4 n0 = make_float4(0.f, 0.f, 0.f, 0.f);
        float4 n1 = make_float4(0.f, 0.f, 0.f, 0.f);
        float nhl = 0.f, nhr = 0.f;
        const int ntile = tile + GRID;
        size_t nbase = 0;
        if (i + 1 < NT) {
            nbase = ((size_t)(ntile >> 1)) * T_LEN + (ntile & 1) * TILE;
            n0 = *reinterpret_cast<const float4*>(x + nbase + p0);
            n1 = *reinterpret_cast<const float4*>(x + nbase + p1);
            if (tid < 3) {
                const int nt0 = (ntile & 1) * TILE;
                if (nt0 > 0)            nhl = x[nbase - 3 + tid];
                if (nt0 + TILE < T_LEN) nhr = x[nbase + TILE + tid];
            }
        }

        // Weights for this row's head: two broadcast LDS.128.
        const int h = row & 15;                 // C=1024 multiple of H=16
        const float4 wa = *reinterpret_cast<const float4*>(&sw[h][0]);
        const float4 wb = *reinterpret_cast<const float4*>(&sw[h][4]);
        const float w0 = wa.x, w1 = wa.y, w2 = wa.z, w3 = wa.w,
                    w4 = wb.x, w5 = wb.y, w6 = wb.z;

        // Chunk 0: outputs [p0 .. p0+3]. Middle float4 == v0 (register reuse).
        {
            const float4 a = *reinterpret_cast<const float4*>(&s[buf][p0]);
            const float4 b = v0;
            const float4 c = *reinterpret_cast<const float4*>(&s[buf][p0 + 8]);
            float4 r;
            r.x = w0*a.y + w1*a.z + w2*a.w + w3*b.x + w4*b.y + w5*b.z + w6*b.w;
            r.y = w0*a.z + w1*a.w + w2*b.x + w3*b.y + w4*b.z + w5*b.w + w6*c.x;
            r.z = w0*a.w + w1*b.x + w2*b.y + w3*b.z + w4*b.w + w5*c.x + w6*c.y;
            r.w = w0*b.x + w1*b.y + w2*b.z + w3*b.w + w4*c.x + w5*c.y + w6*c.z;
            *reinterpret_cast<float4*>(out + base + p0) = r;
        }

        // Chunk 1: outputs [p1 .. p1+3]. Middle float4 == v1.
        {
            const float4 a = *reinterpret_cast<const float4*>(&s[buf][p1]);
            const float4 b = v1;
            const float4 c = *reinterpret_cast<const float4*>(&s[buf][p1 + 8]);
            float4 r;
            r.x = w0*a.y + w1*a.z + w2*a.w + w3*b.x + w4*b.y + w5*b.z + w6*b.w;
            r.y = w0*a.z + w1*a.w + w2*b.x + w3*b.y + w4*b.z + w5*b.w + w6*c.x;
            r.z = w0*a.w + w1*b.x + w2*b.y + w3*b.z + w4*b.w + w5*c.x + w6*c.y;
            r.w = w0*b.x + w1*b.y + w2*b.z + w3*b.w + w4*c.x + w5*c.y + w6*c.z;
            *reinterpret_cast<float4*>(out + base + p1) = r;
        }

        // Rotate pipeline registers; next STS targets the other buffer.
        v0 = n0; v1 = n1; hl = nhl; hr = nhr;
        base = nbase; tile = ntile; buf ^= 1;
    }
}

extern "C" void kernel_launch(void* const* d_in, const int* in_sizes, int n_in,
                              void* d_out, int out_size) {
    const float* x = (const float*)d_in[0];
    const float* w = (const float*)d_in[1];
    float* out = (float*)d_out;

    lconv1d_pipe_kernel<<<GRID, THREADS>>>(x, w, out);
}

// round 15
// speedup vs baseline: 1.1282x; 1.1282x over previous
#include <cuda_runtime.h>
#include <cstdint>

// Depthwise conv1d, K=7, 'same' padding, softmax over taps — single fused kernel.
// x: (B, C, T) fp32; weight: (H, 1, 7); head for channel c is c % H (H=16).
//
// 512 threads x whole-row tile (T=4096): each thread owns 2 float4 chunks
// (MLP=2, register-reused middle chunk — same reg budget as the proven
// TILE=2048/256thr chassis), but ZERO halo LDGs (row ends are just zeros)
// and 100% theoretical occupancy (4 CTAs/SM x 512 thr, 66KB smem).

#define KSIZE 7
#define T_LEN 4096
#define THREADS 512
#define HALF (T_LEN / 2)   // 2048: element stride between a thread's 2 chunks
#define SHIFT 4            // s[SHIFT + i] = x[i]; zeros at s[1..3]

__global__ __launch_bounds__(THREADS, 4)
void lconv1d_row_kernel(const float* __restrict__ x,
                        const float* __restrict__ wraw,
                        float* __restrict__ out) {
    __shared__ float s[SHIFT + T_LEN + 3];
    __shared__ __align__(16) float sw[8];

    const int row = blockIdx.x;               // b*C + c
    const size_t base = (size_t)row * T_LEN;
    const int tid = threadIdx.x;
    const int p0 = tid * 4;
    const int p1 = p0 + HALF;

    // Two independent main-tile loads per thread (MLP=2), aligned STS.128.
    const float4 v0 = *reinterpret_cast<const float4*>(x + base + p0);
    const float4 v1 = *reinterpret_cast<const float4*>(x + base + p1);
    *reinterpret_cast<float4*>(&s[SHIFT + p0]) = v0;
    *reinterpret_cast<float4*>(&s[SHIFT + p1]) = v1;

    // Whole-row tile: halos are pure zero padding, NO halo loads.
    if (tid < 3) {
        s[1 + tid] = 0.f;
        s[SHIFT + T_LEN + tid] = 0.f;
    }

    // Fused softmax over this row's head taps (threads 0..6; __expf/MUFU).
    if (tid < KSIZE) {
        const int h = row & 15;               // C=1024 multiple of H=16
        float v[KSIZE];
        float m = -1e30f;
        #pragma unroll
        for (int k = 0; k < KSIZE; k++) {
            v[k] = __ldg(&wraw[h * KSIZE + k]);
            m = fmaxf(m, v[k]);
        }
        float sum = 0.f;
        #pragma unroll
        for (int k = 0; k < KSIZE; k++) sum += __expf(v[k] - m);
        sw[tid] = __expf(v[tid] - m) / sum;
        if (tid == 0) sw[7] = 0.f;
    }

    __syncthreads();

    const float4 wa = *reinterpret_cast<const float4*>(&sw[0]);
    const float4 wb = *reinterpret_cast<const float4*>(&sw[4]);
    const float w0 = wa.x, w1 = wa.y, w2 = wa.z, w3 = wa.w,
                w4 = wb.x, w5 = wb.y, w6 = wb.z;

    // Chunk 0: outputs [p0 .. p0+3]. Middle float4 == v0 (register reuse).
    {
        const float4 a = *reinterpret_cast<const float4*>(&s[p0]);
        const float4 b = v0;
        const float4 c = *reinterpret_cast<const float4*>(&s[p0 + 8]);
        float4 r;
        r.x = w0*a.y + w1*a.z + w2*a.w + w3*b.x + w4*b.y + w5*b.z + w6*b.w;
        r.y = w0*a.z + w1*a.w + w2*b.x + w3*b.y + w4*b.z + w5*b.w + w6*c.x;
        r.z = w0*a.w + w1*b.x + w2*b.y + w3*b.z + w4*b.w + w5*c.x + w6*c.y;
        r.w = w0*b.x + w1*b.y + w2*b.z + w3*b.w + w4*c.x + w5*c.y + w6*c.z;
        *reinterpret_cast<float4*>(out + base + p0) = r;
    }

    // Chunk 1: outputs [p1 .. p1+3]. Middle float4 == v1.
    {
        const float4 a = *reinterpret_cast<const float4*>(&s[p1]);
        const float4 b = v1;
        const float4 c = *reinterpret_cast<const float4*>(&s[p1 + 8]);
        float4 r;
        r.x = w0*a.y + w1*a.z + w2*a.w + w3*b.x + w4*b.y + w5*b.z + w6*b.w;
        r.y = w0*a.z + w1*a.w + w2*b.x + w3*b.y + w4*b.z + w5*b.w + w6*c.x;
        r.z = w0*a.w + w1*b.x + w2*b.y + w3*b.z + w4*b.w + w5*c.x + w6*c.y;
        r.w = w0*b.x + w1*b.y + w2*b.z + w3*b.w + w4*c.x + w5*c.y + w6*c.z;
        *reinterpret_cast<float4*>(out + base + p1) = r;
    }
}

extern "C" void kernel_launch(void* const* d_in, const int* in_sizes, int n_in,
                              void* d_out, int out_size) {
    const float* x = (const float*)d_in[0];
    const float* w = (const float*)d_in[1];
    float* out = (float*)d_out;

    const int rows = in_sizes[0] / T_LEN;   // B*C = 16384

    lconv1d_row_kernel<<<rows, THREADS>>>(x, w, out);
}

// round 16
// speedup vs baseline: 1.1556x; 1.0243x over previous
#include <cuda_runtime.h>
#include <cstdint>

// Depthwise conv1d, K=7, 'same' padding, softmax over taps — single fused kernel.
// x: (B, C, T) fp32; weight: (H, 1, 7); head for channel c is c % H (H=16).
//
// Best-measured chassis (TILE=2048, 256 thr, 8KB smem, MLP=2, register-reused
// middle chunk) with straggler balancing:
//   - softmax  -> warp 7 (tid 224..230): highest-wid arbiter priority,
//   - halos    -> warp 1 (tid 32..34),
//   - warp 0   -> plain tile work like warps 2..6.
// Block barrier no longer waits on one overloaded warp.

#define KSIZE 7
#define TILE 2048
#define HALF (TILE / 2)
#define THREADS 256
#define SHIFT 4   // s[SHIFT + i] = x[t0 + i]; halo lives at s[1..3]
#define T_LEN 4096

__global__ __launch_bounds__(THREADS)
void lconv1d_fused_kernel(const float* __restrict__ x,
                          const float* __restrict__ wraw,
                          float* __restrict__ out) {
    __shared__ float s[SHIFT + TILE + 3];
    __shared__ __align__(16) float sw[8];

    const int row = blockIdx.y;               // b*C + c
    const int t0  = blockIdx.x * TILE;
    const size_t base = (size_t)row * T_LEN + t0;
    const int tid = threadIdx.x;
    const int p0 = tid * 4;
    const int p1 = p0 + HALF;

    // Softmax on WARP 7 (tid 224..230) — issued before its tile LDGs so the
    // weight-load latency overlaps them; highest-wid warp issues first.
    float wv[KSIZE];
    if (tid >= 224 && tid < 224 + KSIZE) {
        const int h = row & 15;               // C=1024 multiple of H=16
        #pragma unroll
        for (int k = 0; k < KSIZE; k++)
            wv[k] = __ldg(&wraw[h * KSIZE + k]);
    }

    // Two independent main-tile loads per thread (MLP=2), aligned STS.128.
    const float4 v0 = *reinterpret_cast<const float4*>(x + base + p0);
    const float4 v1 = *reinterpret_cast<const float4*>(x + base + p1);
    *reinterpret_cast<float4*>(&s[SHIFT + p0]) = v0;
    *reinterpret_cast<float4*>(&s[SHIFT + p1]) = v1;

    // Halos on WARP 1 (tid 32..34), zero-padded at row boundaries.
    if (tid >= 32 && tid < 35) {
        const int j = tid - 32;               // 0..2
        s[1 + j]            = (t0 > 0)            ? x[base - 3 + j]    : 0.f;
        s[SHIFT + TILE + j] = (t0 + TILE < T_LEN) ? x[base + TILE + j] : 0.f;
    }

    // Softmax math (MUFU) on warp 7, while its tile LDGs are in flight.
    if (tid >= 224 && tid < 224 + KSIZE) {
        float m = -1e30f;
        #pragma unroll
        for (int k = 0; k < KSIZE; k++) m = fmaxf(m, wv[k]);
        float sum = 0.f;
        #pragma unroll
        for (int k = 0; k < KSIZE; k++) sum += __expf(wv[k] - m);
        sw[tid - 224] = __expf(wv[tid - 224] - m) / sum;
        if (tid == 224) sw[7] = 0.f;
    }

    __syncthreads();

    // Weights via two broadcast LDS.128.
    const float4 wa = *reinterpret_cast<const float4*>(&sw[0]);
    const float4 wb = *reinterpret_cast<const float4*>(&sw[4]);
    const float w0 = wa.x, w1 = wa.y, w2 = wa.z, w3 = wa.w,
                w4 = wb.x, w5 = wb.y, w6 = wb.z;

    // Chunk 0: outputs [p0 .. p0+3]. Middle float4 == v0 (register reuse).
    {
        const float4 a = *reinterpret_cast<const float4*>(&s[p0]);
        const float4 b = v0;
        const float4 c = *reinterpret_cast<const float4*>(&s[p0 + 8]);
        float4 r;
        r.x = w0*a.y + w1*a.z + w2*a.w + w3*b.x + w4*b.y + w5*b.z + w6*b.w;
        r.y = w0*a.z + w1*a.w + w2*b.x + w3*b.y + w4*b.z + w5*b.w + w6*c.x;
        r.z = w0*a.w + w1*b.x + w2*b.y + w3*b.z + w4*b.w + w5*c.x + w6*c.y;
        r.w = w0*b.x + w1*b.y + w2*b.z + w3*b.w + w4*c.x + w5*c.y + w6*c.z;
        *reinterpret_cast<float4*>(out + base + p0) = r;
    }

    // Chunk 1: outputs [p1 .. p1+3]. Middle float4 == v1.
    {
        const float4 a = *reinterpret_cast<const float4*>(&s[p1]);
        const float4 b = v1;
        const float4 c = *reinterpret_cast<const float4*>(&s[p1 + 8]);
        float4 r;
        r.x = w0*a.y + w1*a.z + w2*a.w + w3*b.x + w4*b.y + w5*b.z + w6*b.w;
        r.y = w0*a.z + w1*a.w + w2*b.x + w3*b.y + w4*b.z + w5*b.w + w6*c.x;
        r.z = w0*a.w + w1*b.x + w2*b.y + w3*b.z + w4*b.w + w5*c.x + w6*c.y;
        r.w = w0*b.x + w1*b.y + w2*b.z + w3*b.w + w4*c.x + w5*c.y + w6*c.z;
        *reinterpret_cast<float4*>(out + base + p1) = r;
    }
}

extern "C" void kernel_launch(void* const* d_in, const int* in_sizes, int n_in,
                              void* d_out, int out_size) {
    const float* x = (const float*)d_in[0];
    const float* w = (const float*)d_in[1];
    float* out = (float*)d_out;

    const int rows = in_sizes[0] / T_LEN;   // B*C = 16384

    dim3 grid(T_LEN / TILE, rows);          // (2, 16384)
    lconv1d_fused_kernel<<<grid, THREADS>>>(x, w, out);
}

// round 17
// speedup vs baseline: 1.1570x; 1.0012x over previous
#include <cuda_runtime.h>
#include <cstdint>

// Depthwise conv1d, K=7, 'same' padding, softmax over taps — single fused kernel.
// x: (B, C, T) fp32; weight: (H, 1, 7); head for channel c is c % H (H=16).
//
// Best-measured chassis (R16: 75.9us kernel, DRAM 80.5%):
//   TILE=2048, 256 thr, 8KB smem, MLP=2, register-reused middle chunk,
//   softmax on warp 7 (highest arbiter priority), halos on warp 1,
//   warp 0 does plain tile work. Micro-trims: single __expf per lane
//   (e reused for both sum and numerator), lane 7 zeroes sw[7] itself.

#define KSIZE 7
#define TILE 2048
#define HALF (TILE / 2)
#define THREADS 256
#define SHIFT 4   // s[SHIFT + i] = x[t0 + i]; halo lives at s[1..3]
#define T_LEN 4096

__global__ __launch_bounds__(THREADS)
void lconv1d_fused_kernel(const float* __restrict__ x,
                          const float* __restrict__ wraw,
                          float* __restrict__ out) {
    __shared__ float s[SHIFT + TILE + 3];
    __shared__ __align__(16) float sw[8];

    const int row = blockIdx.y;               // b*C + c
    const int t0  = blockIdx.x * TILE;
    const size_t base = (size_t)row * T_LEN + t0;
    const int tid = threadIdx.x;
    const int p0 = tid * 4;
    const int p1 = p0 + HALF;

    // Weight loads on WARP 7 (tid 224..230), issued before its tile LDGs.
    float wv[KSIZE];
    if (tid >= 224 && tid < 224 + KSIZE) {
        const int h = row & 15;               // C=1024 multiple of H=16
        #pragma unroll
        for (int k = 0; k < KSIZE; k++)
            wv[k] = __ldg(&wraw[h * KSIZE + k]);
    }

    // Two independent main-tile loads per thread (MLP=2), aligned STS.128.
    const float4 v0 = *reinterpret_cast<const float4*>(x + base + p0);
    const float4 v1 = *reinterpret_cast<const float4*>(x + base + p1);
    *reinterpret_cast<float4*>(&s[SHIFT + p0]) = v0;
    *reinterpret_cast<float4*>(&s[SHIFT + p1]) = v1;

    // Halos on WARP 1 (tid 32..34), zero-padded at row boundaries.
    if (tid >= 32 && tid < 35) {
        const int j = tid - 32;               // 0..2
        s[1 + j]            = (t0 > 0)            ? x[base - 3 + j]    : 0.f;
        s[SHIFT + TILE + j] = (t0 + TILE < T_LEN) ? x[base + TILE + j] : 0.f;
    }

    // Softmax math on warp 7 while its tile LDGs are in flight.
    // One __expf per lane: e[k] computed once, own-lane value reused.
    if (tid >= 224 && tid < 224 + KSIZE) {
        const int lane = tid - 224;
        float m = -1e30f;
        #pragma unroll
        for (int k = 0; k < KSIZE; k++) m = fmaxf(m, wv[k]);
        float e[KSIZE];
        float sum = 0.f;
        #pragma unroll
        for (int k = 0; k < KSIZE; k++) { e[k] = __expf(wv[k] - m); sum += e[k]; }
        sw[lane] = e[lane] / sum;
    } else if (tid == 224 + KSIZE) {          // lane 7 handles the pad slot
        sw[7] = 0.f;
    }

    __syncthreads();

    // Weights via two broadcast LDS.128.
    const float4 wa = *reinterpret_cast<const float4*>(&sw[0]);
    const float4 wb = *reinterpret_cast<const float4*>(&sw[4]);
    const float w0 = wa.x, w1 = wa.y, w2 = wa.z, w3 = wa.w,
                w4 = wb.x, w5 = wb.y, w6 = wb.z;

    // Chunk 0: outputs [p0 .. p0+3]. Middle float4 == v0 (register reuse).
    {
        const float4 a = *reinterpret_cast<const float4*>(&s[p0]);
        const float4 b = v0;
        const float4 c = *reinterpret_cast<const float4*>(&s[p0 + 8]);
        float4 r;
        r.x = w0*a.y + w1*a.z + w2*a.w + w3*b.x + w4*b.y + w5*b.z + w6*b.w;
        r.y = w0*a.z + w1*a.w + w2*b.x + w3*b.y + w4*b.z + w5*b.w + w6*c.x;
        r.z = w0*a.w + w1*b.x + w2*b.y + w3*b.z + w4*b.w + w5*c.x + w6*c.y;
        r.w = w0*b.x + w1*b.y + w2*b.z + w3*b.w + w4*c.x + w5*c.y + w6*c.z;
        *reinterpret_cast<float4*>(out + base + p0) = r;
    }

    // Chunk 1: outputs [p1 .. p1+3]. Middle float4 == v1.
    {
        const float4 a = *reinterpret_cast<const float4*>(&s[p1]);
        const float4 b = v1;
        const float4 c = *reinterpret_cast<const float4*>(&s[p1 + 8]);
        float4 r;
        r.x = w0*a.y + w1*a.z + w2*a.w + w3*b.x + w4*b.y + w5*b.z + w6*b.w;
        r.y = w0*a.z + w1*a.w + w2*b.x + w3*b.y + w4*b.z + w5*b.w + w6*c.x;
        r.z = w0*a.w + w1*b.x + w2*b.y + w3*b.z + w4*b.w + w5*c.x + w6*c.y;
        r.w = w0*b.x + w1*b.y + w2*b.z + w3*b.w + w4*c.x + w5*c.y + w6*c.z;
        *reinterpret_cast<float4*>(out + base + p1) = r;
    }
}

extern "C" void kernel_launch(void* const* d_in, const int* in_sizes, int n_in,
                              void* d_out, int out_size) {
    const float* x = (const float*)d_in[0];
    const float* w = (const float*)d_in[1];
    float* out = (float*)d_out;

    const int rows = in_sizes[0] / T_LEN;   // B*C = 16384

    dim3 grid(T_LEN / TILE, rows);          // (2, 16384)
    lconv1d_fused_kernel<<<grid, THREADS>>>(x, w, out);
}